// round 2
// baseline (speedup 1.0000x reference)
#include <cuda_runtime.h>
#include <cuda_bf16.h>
#include <stdint.h>

#define SDIM    16
#define KDIM    4096
#define ODIM    14336
#define GSIZE   256
#define NGROUPS (KDIM / GSIZE)   // 16
#define TILE_O  32
#define NTHREADS 128
#define STRIDE  264              // bf16 elems per smem row (132 words, +4 banks/row -> conflict-free frags)

static __device__ __forceinline__ uint32_t packbf(__nv_bfloat16 a, __nv_bfloat16 b) {
    __nv_bfloat162 t = __halves2bfloat162(a, b);
    return *reinterpret_cast<uint32_t*>(&t);
}

static __device__ __forceinline__ void mma16816(
    float& d0, float& d1, float& d2, float& d3,
    uint32_t a0, uint32_t a1, uint32_t a2, uint32_t a3,
    uint32_t b0, uint32_t b1)
{
    asm volatile(
        "mma.sync.aligned.m16n8k16.row.col.f32.bf16.bf16.f32 "
        "{%0,%1,%2,%3}, {%4,%5,%6,%7}, {%8,%9}, {%0,%1,%2,%3};\n"
        : "+f"(d0), "+f"(d1), "+f"(d2), "+f"(d3)
        : "r"(a0), "r"(a1), "r"(a2), "r"(a3), "r"(b0), "r"(b1));
}

__global__ void __launch_bounds__(NTHREADS, 3)
qlinear_int4_kernel(const float* __restrict__ x,
                    const float* __restrict__ w,
                    float* __restrict__ out)
{
    __shared__ __nv_bfloat16 sxh[SDIM][STRIDE];   // x high bf16
    __shared__ __nv_bfloat16 sxl[SDIM][STRIDE];   // x low  bf16 (residual)
    __shared__ __nv_bfloat16 swq[TILE_O][STRIDE]; // quantized w_int as bf16
    __shared__ float sscale[TILE_O];

    const int tid  = threadIdx.x;
    const int lane = tid & 31;
    const int wid  = tid >> 5;       // warp 0..3, owns n8 tile wid
    const int gid  = lane >> 2;      // 0..7
    const int tg   = lane & 3;       // 0..3
    const int obase = blockIdx.x * TILE_O;

    // W tile load mapping: 4 threads per output row, 64B contiguous per row per instr
    const int wr = tid >> 2;         // row in tile 0..31
    const int wc = tid & 3;          // chunk 0..3
    const float* wrow = w + (size_t)(obase + wr) * KDIM;

    // x tile load mapping: 8 threads per s-row, 128B contiguous per row per instr
    const int xs = tid >> 3;         // 0..15
    const int xc = tid & 7;          // 0..7
    const float* xrow = x + (size_t)xs * KDIM;

    float facc0 = 0.f, facc1 = 0.f, facc2 = 0.f, facc3 = 0.f;

    // smem base pointers for MMA fragment loads
    const int nrow = wid * 8 + gid;  // o column within tile for B fragments
    const __nv_bfloat16* pxh0 = &sxh[gid][2 * tg];
    const __nv_bfloat16* pxh1 = &sxh[gid + 8][2 * tg];
    const __nv_bfloat16* pxl0 = &sxl[gid][2 * tg];
    const __nv_bfloat16* pxl1 = &sxl[gid + 8][2 * tg];
    const __nv_bfloat16* pwq  = &swq[nrow][2 * tg];

    for (int g = 0; g < NGROUPS; ++g) {
        const int kbase = g * GSIZE;

        // ---- global loads into registers (overlaps previous group's MMA) ----
        float4 wv[16];
        #pragma unroll
        for (int i = 0; i < 16; ++i)
            wv[i] = *(const float4*)(wrow + kbase + (wc + 4 * i) * 4);

        float4 xv[8];
        #pragma unroll
        for (int i = 0; i < 8; ++i)
            xv[i] = *(const float4*)(xrow + kbase + (xc + 8 * i) * 4);

        // ---- per-row group max (exact: thread-local + 2x shfl across the 4-lane row group)
        float m = 0.f;
        #pragma unroll
        for (int i = 0; i < 16; ++i) {
            m = fmaxf(m, fabsf(wv[i].x));
            m = fmaxf(m, fabsf(wv[i].y));
            m = fmaxf(m, fabsf(wv[i].z));
            m = fmaxf(m, fabsf(wv[i].w));
        }
        m = fmaxf(m, __shfl_xor_sync(0xffffffffu, m, 1));
        m = fmaxf(m, __shfl_xor_sync(0xffffffffu, m, 2));
        const float scale = fmaxf(m / 7.0f, 1e-9f);
        const float rcp   = 1.0f / scale;

        __syncthreads();   // previous group's MMA reads done before smem overwrite

        // ---- quantize W -> bf16 w_int into smem ----
        #pragma unroll
        for (int i = 0; i < 16; ++i) {
            const int col = (wc + 4 * i) * 4;
            const float4 v = wv[i];
            float q0 = fminf(fmaxf(rintf(v.x * rcp), -8.f), 7.f);
            float q1 = fminf(fmaxf(rintf(v.y * rcp), -8.f), 7.f);
            float q2 = fminf(fmaxf(rintf(v.z * rcp), -8.f), 7.f);
            float q3 = fminf(fmaxf(rintf(v.w * rcp), -8.f), 7.f);
            uint2 pk;
            pk.x = packbf(__float2bfloat16_rn(q0), __float2bfloat16_rn(q1));
            pk.y = packbf(__float2bfloat16_rn(q2), __float2bfloat16_rn(q3));
            *(uint2*)&swq[wr][col] = pk;
        }
        if (wc == 0) sscale[wr] = scale;

        // ---- split x into bf16 hi/lo into smem ----
        #pragma unroll
        for (int i = 0; i < 8; ++i) {
            const int col = (xc + 8 * i) * 4;
            const float4 v = xv[i];
            __nv_bfloat16 hx = __float2bfloat16_rn(v.x);
            __nv_bfloat16 hy = __float2bfloat16_rn(v.y);
            __nv_bfloat16 hz = __float2bfloat16_rn(v.z);
            __nv_bfloat16 hw = __float2bfloat16_rn(v.w);
            uint2 hv;
            hv.x = packbf(hx, hy);
            hv.y = packbf(hz, hw);
            *(uint2*)&sxh[xs][col] = hv;
            uint2 lv;
            lv.x = packbf(__float2bfloat16_rn(v.x - __bfloat162float(hx)),
                          __float2bfloat16_rn(v.y - __bfloat162float(hy)));
            lv.y = packbf(__float2bfloat16_rn(v.z - __bfloat162float(hz)),
                          __float2bfloat16_rn(v.w - __bfloat162float(hw)));
            *(uint2*)&sxl[xs][col] = lv;
        }

        __syncthreads();

        // ---- MMA phase: 16 k-steps x (hi + lo), group-local fp32 accumulators ----
        float g0 = 0.f, g1 = 0.f, g2 = 0.f, g3 = 0.f;
        #pragma unroll
        for (int ks = 0; ks < 16; ++ks) {
            const int kk = ks * 16;
            const uint32_t b0 = *(const uint32_t*)(pwq + kk);
            const uint32_t b1 = *(const uint32_t*)(pwq + kk + 8);

            uint32_t a0 = *(const uint32_t*)(pxh0 + kk);
            uint32_t a1 = *(const uint32_t*)(pxh1 + kk);
            uint32_t a2 = *(const uint32_t*)(pxh0 + kk + 8);
            uint32_t a3 = *(const uint32_t*)(pxh1 + kk + 8);
            mma16816(g0, g1, g2, g3, a0, a1, a2, a3, b0, b1);

            a0 = *(const uint32_t*)(pxl0 + kk);
            a1 = *(const uint32_t*)(pxl1 + kk);
            a2 = *(const uint32_t*)(pxl0 + kk + 8);
            a3 = *(const uint32_t*)(pxl1 + kk + 8);
            mma16816(g0, g1, g2, g3, a0, a1, a2, a3, b0, b1);
        }

        // scale per output column (o), accumulate into final
        const float se = sscale[wid * 8 + 2 * tg];
        const float so = sscale[wid * 8 + 2 * tg + 1];
        facc0 += se * g0;
        facc1 += so * g1;
        facc2 += se * g2;
        facc3 += so * g3;
    }

    // ---- epilogue: D[s][o] -> out[s*ODIM + o] ----
    const int ocol = obase + wid * 8 + 2 * tg;
    const int r0 = gid;
    const int r1 = gid + 8;
    *(float2*)(out + (size_t)r0 * ODIM + ocol) = make_float2(facc0, facc1);
    *(float2*)(out + (size_t)r1 * ODIM + ocol) = make_float2(facc2, facc3);
}

extern "C" void kernel_launch(void* const* d_in, const int* in_sizes, int n_in,
                              void* d_out, int out_size)
{
    (void)in_sizes; (void)n_in; (void)out_size;
    const float* x = (const float*)d_in[0];   // [1,16,4096]
    const float* w = (const float*)d_in[1];   // [14336,4096]
    float* out = (float*)d_out;               // [1,16,14336]

    dim3 grid(ODIM / TILE_O);  // 448
    dim3 block(NTHREADS);      // 128
    qlinear_int4_kernel<<<grid, block>>>(x, w, out);
}

// round 3
// speedup vs baseline: 1.0395x; 1.0395x over previous
#include <cuda_runtime.h>
#include <cuda_bf16.h>
#include <stdint.h>

#define SDIM    16
#define KDIM    4096
#define ODIM    14336
#define GSIZE   256
#define NGROUPS (KDIM / GSIZE)   // 16
#define TILE_O  32
#define NTHREADS 128
#define STRIDE  264              // bf16 elems per smem row; 528B row stride -> 4-bank shift/row, LDSM conflict-free

static __device__ __forceinline__ uint32_t packbf(__nv_bfloat16 a, __nv_bfloat16 b) {
    __nv_bfloat162 t = __halves2bfloat162(a, b);
    return *reinterpret_cast<uint32_t*>(&t);
}

static __device__ __forceinline__ void mma16816(
    float& d0, float& d1, float& d2, float& d3,
    uint32_t a0, uint32_t a1, uint32_t a2, uint32_t a3,
    uint32_t b0, uint32_t b1)
{
    asm volatile(
        "mma.sync.aligned.m16n8k16.row.col.f32.bf16.bf16.f32 "
        "{%0,%1,%2,%3}, {%4,%5,%6,%7}, {%8,%9}, {%0,%1,%2,%3};\n"
        : "+f"(d0), "+f"(d1), "+f"(d2), "+f"(d3)
        : "r"(a0), "r"(a1), "r"(a2), "r"(a3), "r"(b0), "r"(b1));
}

static __device__ __forceinline__ void ldsm_x4(
    uint32_t& r0, uint32_t& r1, uint32_t& r2, uint32_t& r3, uint32_t saddr)
{
    asm volatile("ldmatrix.sync.aligned.m8n8.x4.shared.b16 {%0,%1,%2,%3}, [%4];\n"
        : "=r"(r0), "=r"(r1), "=r"(r2), "=r"(r3) : "r"(saddr));
}

static __device__ __forceinline__ void ldsm_x2(
    uint32_t& r0, uint32_t& r1, uint32_t saddr)
{
    asm volatile("ldmatrix.sync.aligned.m8n8.x2.shared.b16 {%0,%1}, [%2];\n"
        : "=r"(r0), "=r"(r1) : "r"(saddr));
}

__global__ void __launch_bounds__(NTHREADS, 3)
qlinear_int4_kernel(const float* __restrict__ x,
                    const float* __restrict__ w,
                    float* __restrict__ out)
{
    __shared__ __nv_bfloat16 sxh[SDIM][STRIDE];   // x high bf16
    __shared__ __nv_bfloat16 sxl[SDIM][STRIDE];   // x low  bf16 (residual)
    __shared__ __nv_bfloat16 swq[TILE_O][STRIDE]; // quantized w_int as bf16
    __shared__ float sscale[TILE_O];

    const int tid  = threadIdx.x;
    const int lane = tid & 31;
    const int wid  = tid >> 5;       // warp 0..3, owns n8 tile wid
    const int tg   = lane & 3;       // 0..3
    const int gid  = lane >> 2;      // 0..7
    const int obase = blockIdx.x * TILE_O;

    // W tile load mapping: 4 threads per output row, 64B contiguous per row per instr
    const int wr = tid >> 2;         // row in tile 0..31
    const int wc = tid & 3;          // chunk 0..3
    const float* wrow = w + (size_t)(obase + wr) * KDIM;

    // x tile load mapping: 8 threads per s-row, 128B contiguous per row per instr
    const int xs = tid >> 3;         // 0..15
    const int xc = tid & 7;          // 0..7
    const float* xrow = x + (size_t)xs * KDIM;

    float facc0 = 0.f, facc1 = 0.f, facc2 = 0.f, facc3 = 0.f;

    // ldmatrix base addresses (shared space)
    // A (16x16): lanes 0-15 -> row (lane&15) at col 0; lanes 16-31 -> same rows at col 8
    const uint32_t a_xh = (uint32_t)__cvta_generic_to_shared(&sxh[lane & 15][8 * (lane >> 4)]);
    const uint32_t a_xl = (uint32_t)__cvta_generic_to_shared(&sxl[lane & 15][8 * (lane >> 4)]);
    // B (8x16): lanes 0-7 -> rows (o) 0-7 col 0; lanes 8-15 -> col 8
    const uint32_t a_b  = (uint32_t)__cvta_generic_to_shared(&swq[wid * 8 + (lane & 7)][8 * ((lane >> 3) & 1)]);

    // ---- prologue: load group 0 ----
    float4 wv[16];
    float4 xv[8];
    #pragma unroll
    for (int i = 0; i < 16; ++i)
        wv[i] = *(const float4*)(wrow + (wc + 4 * i) * 4);
    #pragma unroll
    for (int i = 0; i < 8; ++i)
        xv[i] = *(const float4*)(xrow + (xc + 8 * i) * 4);

    for (int g = 0; g < NGROUPS; ++g) {
        // ---- per-row group max (exact: thread-local + 2x shfl across the 4-lane row group)
        float m = 0.f;
        #pragma unroll
        for (int i = 0; i < 16; ++i) {
            m = fmaxf(m, fabsf(wv[i].x));
            m = fmaxf(m, fabsf(wv[i].y));
            m = fmaxf(m, fabsf(wv[i].z));
            m = fmaxf(m, fabsf(wv[i].w));
        }
        m = fmaxf(m, __shfl_xor_sync(0xffffffffu, m, 1));
        m = fmaxf(m, __shfl_xor_sync(0xffffffffu, m, 2));
        const float scale = fmaxf(m / 7.0f, 1e-9f);
        const float rcp   = 1.0f / scale;

        __syncthreads();   // previous group's LDSM reads done before smem overwrite

        // ---- quantize W -> bf16 w_int into smem ----
        #pragma unroll
        for (int i = 0; i < 16; ++i) {
            const int col = (wc + 4 * i) * 4;
            const float4 v = wv[i];
            float q0 = fminf(fmaxf(rintf(v.x * rcp), -8.f), 7.f);
            float q1 = fminf(fmaxf(rintf(v.y * rcp), -8.f), 7.f);
            float q2 = fminf(fmaxf(rintf(v.z * rcp), -8.f), 7.f);
            float q3 = fminf(fmaxf(rintf(v.w * rcp), -8.f), 7.f);
            uint2 pk;
            pk.x = packbf(__float2bfloat16_rn(q0), __float2bfloat16_rn(q1));
            pk.y = packbf(__float2bfloat16_rn(q2), __float2bfloat16_rn(q3));
            *(uint2*)&swq[wr][col] = pk;
        }
        if (wc == 0) sscale[wr] = scale;

        // ---- split x into bf16 hi/lo into smem ----
        #pragma unroll
        for (int i = 0; i < 8; ++i) {
            const int col = (xc + 8 * i) * 4;
            const float4 v = xv[i];
            __nv_bfloat16 hx = __float2bfloat16_rn(v.x);
            __nv_bfloat16 hy = __float2bfloat16_rn(v.y);
            __nv_bfloat16 hz = __float2bfloat16_rn(v.z);
            __nv_bfloat16 hw = __float2bfloat16_rn(v.w);
            uint2 hv;
            hv.x = packbf(hx, hy);
            hv.y = packbf(hz, hw);
            *(uint2*)&sxh[xs][col] = hv;
            uint2 lv;
            lv.x = packbf(__float2bfloat16_rn(v.x - __bfloat162float(hx)),
                          __float2bfloat16_rn(v.y - __bfloat162float(hy)));
            lv.y = packbf(__float2bfloat16_rn(v.z - __bfloat162float(hz)),
                          __float2bfloat16_rn(v.w - __bfloat162float(hw)));
            *(uint2*)&sxl[xs][col] = lv;
        }

        __syncthreads();

        // ---- prefetch next group's tiles (overlaps this group's MMA phase) ----
        if (g + 1 < NGROUPS) {
            const int kb = (g + 1) * GSIZE;
            #pragma unroll
            for (int i = 0; i < 16; ++i)
                wv[i] = *(const float4*)(wrow + kb + (wc + 4 * i) * 4);
            #pragma unroll
            for (int i = 0; i < 8; ++i)
                xv[i] = *(const float4*)(xrow + kb + (xc + 8 * i) * 4);
        }

        // ---- MMA phase: 16 k-steps x (hi + lo), group-local fp32 accumulators ----
        float g0 = 0.f, g1 = 0.f, g2 = 0.f, g3 = 0.f;
        #pragma unroll
        for (int ks = 0; ks < 16; ++ks) {
            const uint32_t boff = ks * 32;  // 16 bf16 = 32 bytes per k-step
            uint32_t b0, b1;
            ldsm_x2(b0, b1, a_b + boff);

            uint32_t h0, h1, h2, h3;
            ldsm_x4(h0, h1, h2, h3, a_xh + boff);
            mma16816(g0, g1, g2, g3, h0, h1, h2, h3, b0, b1);

            uint32_t l0, l1, l2, l3;
            ldsm_x4(l0, l1, l2, l3, a_xl + boff);
            mma16816(g0, g1, g2, g3, l0, l1, l2, l3, b0, b1);
        }

        // scale per output column (o), accumulate into final
        const float se = sscale[wid * 8 + 2 * tg];
        const float so = sscale[wid * 8 + 2 * tg + 1];
        facc0 += se * g0;
        facc1 += so * g1;
        facc2 += se * g2;
        facc3 += so * g3;
    }

    // ---- epilogue: D[s][o] -> out[s*ODIM + o] ----
    const int ocol = obase + wid * 8 + 2 * tg;
    const int r0 = gid;
    const int r1 = gid + 8;
    *(float2*)(out + (size_t)r0 * ODIM + ocol) = make_float2(facc0, facc1);
    *(float2*)(out + (size_t)r1 * ODIM + ocol) = make_float2(facc2, facc3);
}

extern "C" void kernel_launch(void* const* d_in, const int* in_sizes, int n_in,
                              void* d_out, int out_size)
{
    (void)in_sizes; (void)n_in; (void)out_size;
    const float* x = (const float*)d_in[0];   // [1,16,4096]
    const float* w = (const float*)d_in[1];   // [14336,4096]
    float* out = (float*)d_out;               // [1,16,14336]

    dim3 grid(ODIM / TILE_O);  // 448
    dim3 block(NTHREADS);      // 128
    qlinear_int4_kernel<<<grid, block>>>(x, w, out);
}